// round 7
// baseline (speedup 1.0000x reference)
#include <cuda_runtime.h>
#include <math.h>

// CroquetGNN: 2-layer GCN, N=100000, E=3200000, feat 3 -> 16 -> 1
// out = sigmoid( GCNConv2( relu( GCNConv1(x) ) ) )
// GCNConv(x) = dinv[d] * segsum_{s->d}( dinv[s]*x[s] ) @ W (+ self loop + b)
//
// Pull-mode: one-pass padded-CSR build (CAP=128/node; graph is uniform random,
// deg~Poisson(32) so overflow is impossible in practice), then warp-per-node
// gather+reduce with fused epilogues. No aggregation atomics at all.

#define MAXN 100000
#define CAP 128          // padded row capacity (Poisson(32): P(deg>128) ~ 1e-40)
#define TB 256

// ---- scratch (static device globals, BSS-zeroed at load; no allocation) ----
__device__ int    g_cnt[MAXN];        // degree counter (reset in k_layer2)
__device__ int    g_csr[MAXN * CAP];  // padded adjacency: src lists per dst (51.2MB)
__device__ float  g_dinv[MAXN];       // rsqrt(deg+1)
__device__ float4 g_xd[MAXN];         // dinv[i] * x[i] (padded)
__device__ float  g_gd[MAXN];         // dinv[i]*(relu(conv1).W2)

// per-block dtype detect from INPUT only: int64 LE with values < 2^31 has zero hi words
__device__ __forceinline__ int detect64_block(const int* __restrict__ idx) {
    __shared__ int s64;
    if (threadIdx.x < 32) {
        int hi = __ldg(&idx[2 * threadIdx.x + 1]);
        unsigned m = __ballot_sync(0xFFFFFFFFu, hi == 0);
        if (threadIdx.x == 0) s64 = (m == 0xFFFFFFFFu);
    }
    __syncthreads();
    return s64;
}

// ---- k_scatter: one pass — count degree AND build padded CSR ----
__global__ void __launch_bounds__(TB) k_scatter(const int* __restrict__ idx, int E) {
    int is64 = detect64_block(idx);
    int e = blockIdx.x * TB + threadIdx.x;
    if (e >= E) return;
    int s, d;
    if (is64) {
        const long long* __restrict__ p = (const long long*)idx;
        s = (int)__ldg(&p[e]);
        d = (int)__ldg(&p[E + e]);
    } else {
        s = __ldg(&idx[e]);
        d = __ldg(&idx[E + e]);
    }
    int pos = atomicAdd(&g_cnt[d], 1);
    if (pos < CAP) g_csr[d * CAP + pos] = s;   // guard: never corrupt neighbors
}

// ---- k_xd: dinv = rsqrt(deg+1); xd = dinv*x  (cnt NOT reset here; layers need it) ----
__global__ void __launch_bounds__(TB) k_xd(const float* __restrict__ x, int N) {
    int i = blockIdx.x * TB + threadIdx.x;
    if (i >= N) return;
    float di = rsqrtf((float)(g_cnt[i] + 1));   // +1 self loop
    g_dinv[i] = di;
    g_xd[i] = make_float4(x[3 * i] * di, x[3 * i + 1] * di, x[3 * i + 2] * di, 0.f);
}

// ---- k_layer1: warp-per-node pull aggregation + fused conv1 epilogue -> gd ----
__global__ void __launch_bounds__(TB) k_layer1(const float* __restrict__ W1,
                                               const float* __restrict__ b1,
                                               const float* __restrict__ W2, int N) {
    __shared__ float sW1[48], sb1[16], sW2[16];
    int t = threadIdx.x;
    if (t < 48) sW1[t] = __ldg(&W1[t]);
    if (t < 16) { sb1[t] = __ldg(&b1[t]); sW2[t] = __ldg(&W2[t]); }
    __syncthreads();

    int lane = t & 31;
    int node = (blockIdx.x * TB + t) >> 5;
    if (node >= N) return;

    int deg = min(g_cnt[node], CAP);
    const int* __restrict__ row = &g_csr[node * CAP];
    float a0 = 0.f, a1 = 0.f, a2 = 0.f;
    for (int base = 0; base < deg; base += 32) {
        if (base + lane < deg) {
            float4 v = g_xd[row[base + lane]];
            a0 += v.x; a1 += v.y; a2 += v.z;
        }
    }
#pragma unroll
    for (int o = 16; o; o >>= 1) {
        a0 += __shfl_xor_sync(0xFFFFFFFFu, a0, o);
        a1 += __shfl_xor_sync(0xFFFFFFFFu, a1, o);
        a2 += __shfl_xor_sync(0xFFFFFFFFu, a2, o);
    }
    float di = g_dinv[node];          // uniform-address loads: 1 request/warp
    float4 xd = g_xd[node];
    // self-loop contributes dinv^2 * x = dinv * xd
    float v0 = di * (a0 + xd.x);
    float v1 = di * (a1 + xd.y);
    float v2 = di * (a2 + xd.z);
    float p = 0.f;
    if (lane < 16) {                  // one hidden channel per lane
        float h = fmaf(v0, sW1[lane], fmaf(v1, sW1[16 + lane],
                  fmaf(v2, sW1[32 + lane], sb1[lane])));
        h = fmaxf(h, 0.f);
        p = h * sW2[lane];
    }
#pragma unroll
    for (int o = 16; o; o >>= 1) p += __shfl_xor_sync(0xFFFFFFFFu, p, o);
    if (lane == 0) g_gd[node] = p * di;
}

// ---- k_layer2: warp-per-node pull of gd + fused sigmoid; resets cnt (replay-safe) ----
__global__ void __launch_bounds__(TB) k_layer2(const float* __restrict__ b2,
                                               float* __restrict__ out, int N) {
    int t = threadIdx.x;
    int lane = t & 31;
    int node = (blockIdx.x * TB + t) >> 5;
    if (node >= N) return;

    int deg = min(g_cnt[node], CAP);
    const int* __restrict__ row = &g_csr[node * CAP];
    float a = 0.f;
    for (int base = 0; base < deg; base += 32) {
        if (base + lane < deg) a += g_gd[row[base + lane]];
    }
#pragma unroll
    for (int o = 16; o; o >>= 1) a += __shfl_xor_sync(0xFFFFFFFFu, a, o);
    if (lane == 0) {
        g_cnt[node] = 0;              // consumer reset for next replay
        float di = g_dinv[node];
        float s = di * (a + g_gd[node]) + __ldg(&b2[0]);
        out[node] = 1.0f / (1.0f + expf(-s));
    }
}

extern "C" void kernel_launch(void* const* d_in, const int* in_sizes, int n_in,
                              void* d_out, int out_size) {
    const float* x   = (const float*)d_in[0];
    const int*   idx = (const int*)d_in[1];   // int32 or int64 (device-detected)
    const float* W1  = (const float*)d_in[2];
    const float* b1  = (const float*)d_in[3];
    const float* W2  = (const float*)d_in[4];
    const float* b2  = (const float*)d_in[5];
    float* out = (float*)d_out;

    int N_ = in_sizes[0] / 3;   // 100000
    int E_ = in_sizes[1] / 2;   // 3200000

    int nb_e = (E_ + TB - 1) / TB;
    int nb_n = (N_ + TB - 1) / TB;
    int nb_w = (N_ * 32 + TB - 1) / TB;   // warp-per-node grids

    k_scatter<<<nb_e, TB>>>(idx, E_);
    k_xd    <<<nb_n, TB>>>(x, N_);
    k_layer1<<<nb_w, TB>>>(W1, b1, W2, N_);
    k_layer2<<<nb_w, TB>>>(b2, out, N_);
}

// round 8
// speedup vs baseline: 1.2191x; 1.2191x over previous
#include <cuda_runtime.h>
#include <math.h>

// CroquetGNN: 2-layer GCN, N=100000, E=3200000, feat 3 -> 16 -> 1
// out = sigmoid( GCNConv2( relu( GCNConv1(x) ) ) )
// GCNConv(x) = dinv[d] * segsum_{s->d}( dinv[s]*x[s] ) @ W (+ self loop + b)
//
// Pull-mode padded CSR (CAP=128; deg~Poisson(32), overflow impossible in practice),
// aggregation with 8-lane segments per node (4 nodes/warp) so per-node
// reduction+epilogue instructions are SIMT-amortized 4x. No aggregation atomics.

#define MAXN 100000
#define CAP 128          // padded row capacity
#define TB 256
#define SPN 8            // lanes per node segment

// ---- scratch (static device globals, BSS-zeroed at load; no allocation) ----
__device__ int    g_cnt[MAXN];        // degree counter (reset in k_layer2)
__device__ int    g_csr[MAXN * CAP];  // padded adjacency: src lists per dst
__device__ float  g_dinv[MAXN];       // rsqrt(deg+1)
__device__ float4 g_xd[MAXN];         // dinv[i] * x[i] (padded)
__device__ float  g_gd[MAXN];         // dinv[i]*(relu(conv1).W2)

// per-block dtype detect from INPUT only: int64 LE with values < 2^31 has zero hi words
__device__ __forceinline__ int detect64_block(const int* __restrict__ idx) {
    __shared__ int s64;
    if (threadIdx.x < 32) {
        int hi = __ldg(&idx[2 * threadIdx.x + 1]);
        unsigned m = __ballot_sync(0xFFFFFFFFu, hi == 0);
        if (threadIdx.x == 0) s64 = (m == 0xFFFFFFFFu);
    }
    __syncthreads();
    return s64;
}

// ---- k_scatter: one pass — count degree AND build padded CSR ----
__global__ void __launch_bounds__(TB) k_scatter(const int* __restrict__ idx, int E) {
    int is64 = detect64_block(idx);
    int e = blockIdx.x * TB + threadIdx.x;
    if (e >= E) return;
    int s, d;
    if (is64) {
        const long long* __restrict__ p = (const long long*)idx;
        s = (int)__ldg(&p[e]);
        d = (int)__ldg(&p[E + e]);
    } else {
        s = __ldg(&idx[e]);
        d = __ldg(&idx[E + e]);
    }
    int pos = atomicAdd(&g_cnt[d], 1);
    if (pos < CAP) g_csr[d * CAP + pos] = s;   // guard: never corrupt neighbors
}

// ---- k_xd: dinv = rsqrt(deg+1); xd = dinv*x  (cnt kept; layers read it) ----
__global__ void __launch_bounds__(TB) k_xd(const float* __restrict__ x, int N) {
    int i = blockIdx.x * TB + threadIdx.x;
    if (i >= N) return;
    float di = rsqrtf((float)(g_cnt[i] + 1));   // +1 self loop
    g_dinv[i] = di;
    g_xd[i] = make_float4(x[3 * i] * di, x[3 * i + 1] * di, x[3 * i + 2] * di, 0.f);
}

// ---- k_layer1: 8-lane-segment pull + fused conv1 epilogue -> gd ----
__global__ void __launch_bounds__(TB) k_layer1(const float* __restrict__ W1,
                                               const float* __restrict__ b1,
                                               const float* __restrict__ W2, int N) {
    __shared__ float sW1[48], sb1[16], sW2[16];
    int t = threadIdx.x;
    if (t < 48) sW1[t] = __ldg(&W1[t]);
    if (t < 16) { sb1[t] = __ldg(&b1[t]); sW2[t] = __ldg(&W2[t]); }
    __syncthreads();

    int lane8 = t & (SPN - 1);
    int node = (blockIdx.x * TB + t) / SPN;
    bool valid = (node < N);
    int nd = valid ? node : 0;

    int deg = valid ? min(g_cnt[nd], CAP) : 0;
    const int* __restrict__ row = &g_csr[nd * CAP];
    float a0 = 0.f, a1 = 0.f, a2 = 0.f;
    for (int j = lane8; j < deg; j += SPN) {
        float4 v = g_xd[row[j]];
        a0 += v.x; a1 += v.y; a2 += v.z;
    }
    // segment (8-lane) butterfly reduce; all lanes end with the sum
#pragma unroll
    for (int o = SPN / 2; o; o >>= 1) {
        a0 += __shfl_xor_sync(0xFFFFFFFFu, a0, o);
        a1 += __shfl_xor_sync(0xFFFFFFFFu, a1, o);
        a2 += __shfl_xor_sync(0xFFFFFFFFu, a2, o);
    }
    float di = valid ? g_dinv[nd] : 0.f;
    float4 xd = g_xd[nd];
    // self-loop contributes dinv^2 * x = dinv * xd
    float v0 = di * (a0 + xd.x);
    float v1 = di * (a1 + xd.y);
    float v2 = di * (a2 + xd.z);
    // 16 hidden channels over 8 lanes: 2 per lane
    int c0 = lane8, c1 = lane8 + 8;
    float h0 = fmaf(v0, sW1[c0], fmaf(v1, sW1[16 + c0], fmaf(v2, sW1[32 + c0], sb1[c0])));
    float h1 = fmaf(v0, sW1[c1], fmaf(v1, sW1[16 + c1], fmaf(v2, sW1[32 + c1], sb1[c1])));
    float p = fmaxf(h0, 0.f) * sW2[c0] + fmaxf(h1, 0.f) * sW2[c1];
#pragma unroll
    for (int o = SPN / 2; o; o >>= 1) p += __shfl_xor_sync(0xFFFFFFFFu, p, o);
    if (valid && lane8 == 0) g_gd[nd] = p * di;
}

// ---- k_layer2: 8-lane-segment pull of gd + fused sigmoid; resets cnt ----
__global__ void __launch_bounds__(TB) k_layer2(const float* __restrict__ b2,
                                               float* __restrict__ out, int N) {
    float bias2 = __ldg(&b2[0]);
    int t = threadIdx.x;
    int lane8 = t & (SPN - 1);
    int node = (blockIdx.x * TB + t) / SPN;
    bool valid = (node < N);
    int nd = valid ? node : 0;

    int deg = valid ? min(g_cnt[nd], CAP) : 0;
    const int* __restrict__ row = &g_csr[nd * CAP];
    float a = 0.f;
    for (int j = lane8; j < deg; j += SPN) a += g_gd[row[j]];
#pragma unroll
    for (int o = SPN / 2; o; o >>= 1) a += __shfl_xor_sync(0xFFFFFFFFu, a, o);
    if (valid && lane8 == 0) {
        g_cnt[nd] = 0;                 // consumer reset for next replay
        float di = g_dinv[nd];
        float s = di * (a + g_gd[nd]) + bias2;
        out[nd] = 1.0f / (1.0f + expf(-s));
    }
}

extern "C" void kernel_launch(void* const* d_in, const int* in_sizes, int n_in,
                              void* d_out, int out_size) {
    const float* x   = (const float*)d_in[0];
    const int*   idx = (const int*)d_in[1];   // int32 or int64 (device-detected)
    const float* W1  = (const float*)d_in[2];
    const float* b1  = (const float*)d_in[3];
    const float* W2  = (const float*)d_in[4];
    const float* b2  = (const float*)d_in[5];
    float* out = (float*)d_out;

    int N_ = in_sizes[0] / 3;   // 100000
    int E_ = in_sizes[1] / 2;   // 3200000

    int nb_e = (E_ + TB - 1) / TB;
    int nb_n = (N_ + TB - 1) / TB;
    int nb_s = (N_ * SPN + TB - 1) / TB;   // segment-per-node grids

    k_scatter<<<nb_e, TB>>>(idx, E_);
    k_xd    <<<nb_n, TB>>>(x, N_);
    k_layer1<<<nb_s, TB>>>(W1, b1, W2, N_);
    k_layer2<<<nb_s, TB>>>(b2, out, N_);
}